// round 1
// baseline (speedup 1.0000x reference)
#include <cuda_runtime.h>
#include <cuda_bf16.h>
#include <math.h>

// ---------------- problem constants ----------------
#define BATCH 128
#define SEGS  196           // 14*14
#define HW    224
#define NPIX  (HW*HW)       // 50176
#define M_ROWS (BATCH*SEGS) // 25088
#define K0PAD 16
#define NMAX  768
#define BN_EPS 1e-5f
#define OUT_SLICED_ELEMS ((size_t)BATCH*NPIX)   // 6422528

// ---------------- scratch (device globals; no allocation allowed) ----------------
__device__ float g_acc[9 * M_ROWS];            // [feature][b*196+s]
__device__ float g_feat[M_ROWS * K0PAD];       // padded K=16 feature matrix
__device__ float g_w0p[96 * K0PAD];            // padded layer-0 weights
__device__ float g_act0[(size_t)M_ROWS * NMAX];
__device__ float g_act1[(size_t)M_ROWS * NMAX];

// ---------------- segment accumulation ----------------
__global__ __launch_bounds__(256) void seg_acc_kernel(
    const float* __restrict__ x, const int* __restrict__ sliced,
    float* __restrict__ outSliced, float* __restrict__ acc)
{
    __shared__ float s[SEGS * 9];
    const int b = blockIdx.y;
    for (int i = threadIdx.x; i < SEGS * 9; i += blockDim.x) s[i] = 0.0f;
    __syncthreads();

    const int chunk = NPIX / gridDim.x;
    const int p0 = blockIdx.x * chunk;
    const float* xb = x + (size_t)b * 3 * NPIX;
    const int* sb = sliced + (size_t)b * NPIX;
    float* ob = outSliced + (size_t)b * NPIX;

    for (int p = p0 + threadIdx.x; p < p0 + chunk; p += blockDim.x) {
        int sid = sb[p];
        ob[p] = (float)sid;
        float r = (float)(p / HW);
        float c = (float)(p % HW);
        float v0 = xb[p], v1 = xb[NPIX + p], v2 = xb[2 * NPIX + p];
        float* a9 = s + sid * 9;
        atomicAdd(a9 + 0, 1.0f);
        atomicAdd(a9 + 1, r);
        atomicAdd(a9 + 2, c);
        atomicAdd(a9 + 3, v0);
        atomicAdd(a9 + 4, v1);
        atomicAdd(a9 + 5, v2);
        atomicAdd(a9 + 6, v0 * v0);
        atomicAdd(a9 + 7, v1 * v1);
        atomicAdd(a9 + 8, v2 * v2);
    }
    __syncthreads();

    for (int i = threadIdx.x; i < SEGS * 9; i += blockDim.x) {
        int sid = i / 9, f = i % 9;
        float v = s[i];
        if (v != 0.0f) atomicAdd(&acc[(size_t)f * M_ROWS + b * SEGS + sid], v);
    }
}

// ---------------- feature finalize ----------------
__global__ __launch_bounds__(256) void finalize_kernel(
    const float* __restrict__ acc, const float* __restrict__ x,
    float* __restrict__ feat)
{
    int idx = blockIdx.x * blockDim.x + threadIdx.x;
    if (idx >= M_ROWS) return;
    int b = idx / SEGS;

    float cnt  = acc[idx];
    float safe = fmaxf(cnt, 1.0f);
    float inv  = 1.0f / safe;
    float mrow = acc[(size_t)1 * M_ROWS + idx] * inv;
    float mcol = acc[(size_t)2 * M_ROWS + idx] * inv;
    float m0 = acc[(size_t)3 * M_ROWS + idx] * inv;
    float m1 = acc[(size_t)4 * M_ROWS + idx] * inv;
    float m2 = acc[(size_t)5 * M_ROWS + idx] * inv;
    float dn = 1.0f / fmaxf(cnt - 1.0f, 1.0f);
    float v0 = (acc[(size_t)6 * M_ROWS + idx] - cnt * m0 * m0) * dn;
    float v1 = (acc[(size_t)7 * M_ROWS + idx] - cnt * m1 * m1) * dn;
    float v2 = (acc[(size_t)8 * M_ROWS + idx] - cnt * m2 * m2) * dn;
    float sd0 = (cnt > 1.0f) ? sqrtf(fmaxf(v0, 0.0f)) : 0.0f;
    float sd1 = (cnt > 1.0f) ? sqrtf(fmaxf(v1, 0.0f)) : 0.0f;
    float sd2 = (cnt > 1.0f) ? sqrtf(fmaxf(v2, 0.0f)) : 0.0f;

    int ri = min(max((int)mrow, 0), HW - 1);
    int ci = min(max((int)mcol, 0), HW - 1);
    const float* xb = x + (size_t)b * 3 * NPIX;
    int pp = ri * HW + ci;
    float gg0 = xb[pp], gg1 = xb[NPIX + pp], gg2 = xb[2 * NPIX + pp];

    float mask = (cnt > 0.0f) ? 1.0f : 0.0f;
    float* f = feat + (size_t)idx * K0PAD;
    f[0] = mrow * mask; f[1] = mcol * mask;
    f[2] = m0 * mask;   f[3] = m1 * mask;   f[4] = m2 * mask;
    f[5] = sd0 * mask;  f[6] = sd1 * mask;  f[7] = sd2 * mask;
    f[8] = gg0 * mask;  f[9] = gg1 * mask;  f[10] = gg2 * mask;
    f[11] = 0.0f; f[12] = 0.0f; f[13] = 0.0f; f[14] = 0.0f; f[15] = 0.0f;
}

// ---------------- pad layer-0 weights to K=16 ----------------
__global__ void pad_w0_kernel(const float* __restrict__ w0, float* __restrict__ wp)
{
    int i = blockIdx.x * blockDim.x + threadIdx.x;
    if (i >= 96 * K0PAD) return;
    int o = i / K0PAD, c = i % K0PAD;
    wp[i] = (c < 11) ? w0[o * 11 + c] : 0.0f;
}

// ---------------- fused GEMM + BN (+ReLU) ----------------
// C[m][n] = sum_k A[m][k] * W[n][k]; then BN affine, optional ReLU.
// A: [M,K] row-major; W: [N,K] row-major; C: [M,N] row-major.
// Requires: M % 128 == 0, K % 16 == 0, K % 4 == 0, N % 4 == 0.
__global__ __launch_bounds__(256) void gemm_bn_kernel(
    const float* __restrict__ A, const float* __restrict__ W,
    float* __restrict__ C, int M, int N, int K,
    const float* __restrict__ bias, const float* __restrict__ gamma,
    const float* __restrict__ beta, const float* __restrict__ rmean,
    const float* __restrict__ rvar, int relu)
{
    __shared__ float As[16][128];
    __shared__ float Bs[16][128];

    const int tid = threadIdx.x;
    const int bm = blockIdx.y * 128;
    const int bn = blockIdx.x * 128;
    const int tr = (tid / 16) * 8;     // 0..120
    const int tc = (tid % 16) * 8;     // 0..120
    const int lrow = tid >> 2;         // 0..63
    const int lcol = (tid & 3) * 4;    // 0,4,8,12

    float acc[8][8];
    #pragma unroll
    for (int i = 0; i < 8; i++)
        #pragma unroll
        for (int j = 0; j < 8; j++) acc[i][j] = 0.0f;

    for (int kt = 0; kt < K; kt += 16) {
        // A tile (always in-range: M % 128 == 0)
        #pragma unroll
        for (int pass = 0; pass < 2; pass++) {
            int mrow = lrow + pass * 64;
            float4 v = *(const float4*)(A + (size_t)(bm + mrow) * K + kt + lcol);
            As[lcol + 0][mrow] = v.x;
            As[lcol + 1][mrow] = v.y;
            As[lcol + 2][mrow] = v.z;
            As[lcol + 3][mrow] = v.w;
        }
        // W tile (guard n)
        #pragma unroll
        for (int pass = 0; pass < 2; pass++) {
            int nl = lrow + pass * 64;
            int nrow = bn + nl;
            float4 v = make_float4(0.f, 0.f, 0.f, 0.f);
            if (nrow < N) v = *(const float4*)(W + (size_t)nrow * K + kt + lcol);
            Bs[lcol + 0][nl] = v.x;
            Bs[lcol + 1][nl] = v.y;
            Bs[lcol + 2][nl] = v.z;
            Bs[lcol + 3][nl] = v.w;
        }
        __syncthreads();

        #pragma unroll
        for (int k = 0; k < 16; k++) {
            float ra[8], rb[8];
            *(float4*)&ra[0] = *(const float4*)&As[k][tr];
            *(float4*)&ra[4] = *(const float4*)&As[k][tr + 4];
            *(float4*)&rb[0] = *(const float4*)&Bs[k][tc];
            *(float4*)&rb[4] = *(const float4*)&Bs[k][tc + 4];
            #pragma unroll
            for (int i = 0; i < 8; i++)
                #pragma unroll
                for (int j = 0; j < 8; j++)
                    acc[i][j] = fmaf(ra[i], rb[j], acc[i][j]);
        }
        __syncthreads();
    }

    // epilogue: BN affine + optional ReLU, vectorized stores
    #pragma unroll
    for (int j4 = 0; j4 < 8; j4 += 4) {
        int nbase = bn + tc + j4;
        if (nbase >= N) continue;   // N % 4 == 0 -> whole float4 in range
        float sc[4], sh[4];
        #pragma unroll
        for (int j = 0; j < 4; j++) {
            int nn = nbase + j;
            float s = gamma[nn] * rsqrtf(rvar[nn] + BN_EPS);
            sc[j] = s;
            sh[j] = (bias[nn] - rmean[nn]) * s + beta[nn];
        }
        #pragma unroll
        for (int i = 0; i < 8; i++) {
            int m = bm + tr + i;
            float4 o;
            o.x = fmaf(acc[i][j4 + 0], sc[0], sh[0]);
            o.y = fmaf(acc[i][j4 + 1], sc[1], sh[1]);
            o.z = fmaf(acc[i][j4 + 2], sc[2], sh[2]);
            o.w = fmaf(acc[i][j4 + 3], sc[3], sh[3]);
            if (relu) {
                o.x = fmaxf(o.x, 0.f); o.y = fmaxf(o.y, 0.f);
                o.z = fmaxf(o.z, 0.f); o.w = fmaxf(o.w, 0.f);
            }
            *(float4*)(C + (size_t)m * N + nbase) = o;
        }
    }
}

// ---------------- final transpose: [b*196+s][768] -> [b][768][196] ----------------
__global__ __launch_bounds__(256) void transpose_out_kernel(
    const float* __restrict__ in, float* __restrict__ out)
{
    __shared__ float t[32][33];
    const int b = blockIdx.z;
    const int n0 = blockIdx.x * 32;
    const int s0 = blockIdx.y * 32;
    const int x = threadIdx.x;      // 32
    const int y = threadIdx.y;      // 8

    #pragma unroll
    for (int i = y; i < 32; i += 8) {
        int s = s0 + i;
        if (s < SEGS) t[i][x] = in[((size_t)b * SEGS + s) * NMAX + n0 + x];
    }
    __syncthreads();
    #pragma unroll
    for (int i = y; i < 32; i += 8) {
        int n = n0 + i;
        int s = s0 + x;
        if (s < SEGS) out[(size_t)b * NMAX * SEGS + (size_t)n * SEGS + s] = t[x][i];
    }
}

// ---------------- launcher ----------------
extern "C" void kernel_launch(void* const* d_in, const int* in_sizes, int n_in,
                              void* d_out, int out_size)
{
    const float* x      = (const float*)d_in[0];
    const int*   sliced = (const int*)d_in[1];
    const float *W[5], *Bb[5], *G[5], *Be[5], *Rm[5], *Rv[5];
    for (int i = 0; i < 5; i++) {
        int k = 2 + i * 6;
        W[i]  = (const float*)d_in[k + 0];
        Bb[i] = (const float*)d_in[k + 1];
        G[i]  = (const float*)d_in[k + 2];
        Be[i] = (const float*)d_in[k + 3];
        Rm[i] = (const float*)d_in[k + 4];
        Rv[i] = (const float*)d_in[k + 5];
    }
    float* out = (float*)d_out;

    void *accP, *featP, *w0pP, *a0P, *a1P;
    cudaGetSymbolAddress(&accP,  g_acc);
    cudaGetSymbolAddress(&featP, g_feat);
    cudaGetSymbolAddress(&w0pP,  g_w0p);
    cudaGetSymbolAddress(&a0P,   g_act0);
    cudaGetSymbolAddress(&a1P,   g_act1);
    float* acc  = (float*)accP;
    float* feat = (float*)featP;
    float* w0p  = (float*)w0pP;
    float* act0 = (float*)a0P;
    float* act1 = (float*)a1P;

    cudaMemsetAsync(accP, 0, sizeof(float) * 9 * M_ROWS, 0);

    // segment features (also emits (float)sliced into out[0 .. 6422527])
    seg_acc_kernel<<<dim3(8, BATCH), 256>>>(x, sliced, out, acc);
    finalize_kernel<<<(M_ROWS + 255) / 256, 256>>>(acc, x, feat);
    pad_w0_kernel<<<(96 * K0PAD + 255) / 256, 256>>>(W[0], w0p);

    const int MB = M_ROWS / 128;  // 196
    // L0: 16 -> 96 (relu)
    gemm_bn_kernel<<<dim3(1, MB), 256>>>(feat, w0p, act0, M_ROWS, 96, 16,
                                         Bb[0], G[0], Be[0], Rm[0], Rv[0], 1);
    // L1: 96 -> 192 (relu)
    gemm_bn_kernel<<<dim3(2, MB), 256>>>(act0, W[1], act1, M_ROWS, 192, 96,
                                         Bb[1], G[1], Be[1], Rm[1], Rv[1], 1);
    // L2: 192 -> 384 (relu)
    gemm_bn_kernel<<<dim3(3, MB), 256>>>(act1, W[2], act0, M_ROWS, 384, 192,
                                         Bb[2], G[2], Be[2], Rm[2], Rv[2], 1);
    // L3: 384 -> 768 (relu)
    gemm_bn_kernel<<<dim3(6, MB), 256>>>(act0, W[3], act1, M_ROWS, 768, 384,
                                         Bb[3], G[3], Be[3], Rm[3], Rv[3], 1);
    // L4: 768 -> 768 (no relu)
    gemm_bn_kernel<<<dim3(6, MB), 256>>>(act1, W[4], act0, M_ROWS, 768, 768,
                                         Bb[4], G[4], Be[4], Rm[4], Rv[4], 0);

    // transpose into out[6422528 ...]
    transpose_out_kernel<<<dim3(NMAX / 32, (SEGS + 31) / 32, BATCH), dim3(32, 8)>>>(
        act0, out + OUT_SLICED_ELEMS);
}

// round 5
// speedup vs baseline: 2.2400x; 2.2400x over previous
#include <cuda_runtime.h>
#include <cuda_bf16.h>
#include <math.h>
#include <stdint.h>

// ---------------- problem constants ----------------
#define BATCH 128
#define SEGS  196
#define HW    224
#define NPIX  (HW*HW)
#define M_ROWS (BATCH*SEGS)      // 25088
#define BN_EPS 1e-5f
#define OUT_SLICED_ELEMS ((size_t)BATCH*NPIX)

// ================= helpers =================
__device__ __forceinline__ uint32_t smem_u32(const void* p) {
    uint32_t a;
    asm("{ .reg .u64 t; cvta.to.shared.u64 t, %1; cvt.u32.u64 %0, t; }" : "=r"(a) : "l"(p));
    return a;
}
#define SWZ128(off) ((off) ^ (((off) >> 3) & 0x70))

#define CP_ASYNC16(saddr, gptr) \
    asm volatile("cp.async.cg.shared.global [%0], [%1], 16;" :: "r"(saddr), "l"(gptr))
#define CP_COMMIT() asm volatile("cp.async.commit_group;" ::: "memory")
#define CP_WAIT0()  asm volatile("cp.async.wait_group 0;" ::: "memory")
#define CP_WAIT1()  asm volatile("cp.async.wait_group 1;" ::: "memory")

#define LDSM_X4(r, addr) \
    asm volatile("ldmatrix.sync.aligned.m8n8.x4.shared.b16 {%0,%1,%2,%3}, [%4];" \
        : "=r"((r)[0]), "=r"((r)[1]), "=r"((r)[2]), "=r"((r)[3]) : "r"(addr))

__device__ __forceinline__ void mma_bf16(float* c, const uint32_t* a, const uint32_t* b) {
    asm volatile(
        "mma.sync.aligned.m16n8k16.row.col.f32.bf16.bf16.f32 "
        "{%0,%1,%2,%3}, {%4,%5,%6,%7}, {%8,%9}, {%0,%1,%2,%3};"
        : "+f"(c[0]), "+f"(c[1]), "+f"(c[2]), "+f"(c[3])
        : "r"(a[0]), "r"(a[1]), "r"(a[2]), "r"(a[3]), "r"(b[0]), "r"(b[1]));
}

// ================= scratch (device globals) =================
__device__ float g_acc[9 * M_ROWS];
__device__ __nv_bfloat16 g_hi0[(size_t)M_ROWS * 768];
__device__ __nv_bfloat16 g_lo0[(size_t)M_ROWS * 768];
__device__ __nv_bfloat16 g_hi1[(size_t)M_ROWS * 768];
__device__ __nv_bfloat16 g_lo1[(size_t)M_ROWS * 768];
__device__ __nv_bfloat16 g_whi[999424];
__device__ __nv_bfloat16 g_wlo[999424];
__device__ float g_scale[2208];
__device__ float g_shift[2208];

// ================= segment accumulation =================
__global__ __launch_bounds__(256) void seg_acc_kernel(
    const float* __restrict__ x, const int* __restrict__ sliced,
    float* __restrict__ outSliced, float* __restrict__ acc)
{
    __shared__ float s[SEGS * 9];
    const int b = blockIdx.y;
    for (int i = threadIdx.x; i < SEGS * 9; i += blockDim.x) s[i] = 0.0f;
    __syncthreads();

    const int chunk = NPIX / gridDim.x;
    const int p0 = blockIdx.x * chunk;
    const float* xb = x + (size_t)b * 3 * NPIX;
    const int* sb = sliced + (size_t)b * NPIX;
    float* ob = outSliced + (size_t)b * NPIX;

    for (int p = p0 + threadIdx.x; p < p0 + chunk; p += blockDim.x) {
        int sid = sb[p];
        ob[p] = (float)sid;
        float r = (float)(p / HW);
        float c = (float)(p % HW);
        float v0 = xb[p], v1 = xb[NPIX + p], v2 = xb[2 * NPIX + p];
        float* a9 = s + sid * 9;
        atomicAdd(a9 + 0, 1.0f);
        atomicAdd(a9 + 1, r);
        atomicAdd(a9 + 2, c);
        atomicAdd(a9 + 3, v0);
        atomicAdd(a9 + 4, v1);
        atomicAdd(a9 + 5, v2);
        atomicAdd(a9 + 6, v0 * v0);
        atomicAdd(a9 + 7, v1 * v1);
        atomicAdd(a9 + 8, v2 * v2);
    }
    __syncthreads();
    for (int i = threadIdx.x; i < SEGS * 9; i += blockDim.x) {
        int sid = i / 9, f = i % 9;
        float v = s[i];
        if (v != 0.0f) atomicAdd(&acc[(size_t)f * M_ROWS + b * SEGS + sid], v);
    }
}

// ================= finalize -> bf16 hi/lo feature matrix (stride 64) =================
__global__ __launch_bounds__(256) void finalize_kernel(
    const float* __restrict__ acc, const float* __restrict__ x,
    __nv_bfloat16* __restrict__ fhi, __nv_bfloat16* __restrict__ flo)
{
    int idx = blockIdx.x * blockDim.x + threadIdx.x;
    if (idx >= M_ROWS) return;
    int b = idx / SEGS;

    float cnt  = acc[idx];
    float inv  = 1.0f / fmaxf(cnt, 1.0f);
    float mrow = acc[(size_t)1 * M_ROWS + idx] * inv;
    float mcol = acc[(size_t)2 * M_ROWS + idx] * inv;
    float m0 = acc[(size_t)3 * M_ROWS + idx] * inv;
    float m1 = acc[(size_t)4 * M_ROWS + idx] * inv;
    float m2 = acc[(size_t)5 * M_ROWS + idx] * inv;
    float dn = 1.0f / fmaxf(cnt - 1.0f, 1.0f);
    float v0 = (acc[(size_t)6 * M_ROWS + idx] - cnt * m0 * m0) * dn;
    float v1 = (acc[(size_t)7 * M_ROWS + idx] - cnt * m1 * m1) * dn;
    float v2 = (acc[(size_t)8 * M_ROWS + idx] - cnt * m2 * m2) * dn;
    float sd0 = (cnt > 1.0f) ? sqrtf(fmaxf(v0, 0.0f)) : 0.0f;
    float sd1 = (cnt > 1.0f) ? sqrtf(fmaxf(v1, 0.0f)) : 0.0f;
    float sd2 = (cnt > 1.0f) ? sqrtf(fmaxf(v2, 0.0f)) : 0.0f;

    int ri = min(max((int)mrow, 0), HW - 1);
    int ci = min(max((int)mcol, 0), HW - 1);
    const float* xb = x + (size_t)b * 3 * NPIX;
    int pp = ri * HW + ci;
    float mask = (cnt > 0.0f) ? 1.0f : 0.0f;

    float f[11];
    f[0] = mrow * mask; f[1] = mcol * mask;
    f[2] = m0 * mask;   f[3] = m1 * mask;   f[4] = m2 * mask;
    f[5] = sd0 * mask;  f[6] = sd1 * mask;  f[7] = sd2 * mask;
    f[8] = xb[pp] * mask; f[9] = xb[NPIX + pp] * mask; f[10] = xb[2 * NPIX + pp] * mask;

    __nv_bfloat16* ph = fhi + (size_t)idx * 64;
    __nv_bfloat16* pl = flo + (size_t)idx * 64;
    #pragma unroll
    for (int c = 0; c < 11; c++) {
        __nv_bfloat16 h = __float2bfloat16(f[c]);
        ph[c] = h;
        pl[c] = __float2bfloat16(f[c] - __bfloat162float(h));
    }
    for (int c = 11; c < 64; c++) { ph[c] = __float2bfloat16(0.f); pl[c] = __float2bfloat16(0.f); }
}

// ================= weight convert/pad to bf16 hi/lo =================
__global__ void conv_w_kernel(const float* __restrict__ w,
                              __nv_bfloat16* __restrict__ whi, __nv_bfloat16* __restrict__ wlo,
                              int N, int K, int Npad, int Kpad)
{
    int idx = blockIdx.x * blockDim.x + threadIdx.x;
    if (idx >= Npad * Kpad) return;
    int n = idx / Kpad, k = idx % Kpad;
    float v = (n < N && k < K) ? w[n * K + k] : 0.0f;
    __nv_bfloat16 h = __float2bfloat16(v);
    whi[idx] = h;
    wlo[idx] = __float2bfloat16(v - __bfloat162float(h));
}

// ================= BN scale/shift precompute =================
__global__ void bnpar_kernel(const float* __restrict__ g, const float* __restrict__ be,
                             const float* __restrict__ rm, const float* __restrict__ rv,
                             const float* __restrict__ bias, int N,
                             float* __restrict__ sc, float* __restrict__ sh)
{
    int i = blockIdx.x * blockDim.x + threadIdx.x;
    if (i >= N) return;
    float s = g[i] * rsqrtf(rv[i] + BN_EPS);
    sc[i] = s;
    sh[i] = (bias[i] - rm[i]) * s + be[i];
}

// ================= split-bf16 HMMA GEMM + BN epilogue =================
// C[m][n] = sum_k A[m][k]*W[n][k], A=Ahi+Alo, W=Whi+Wlo (3 mma products).
// CTA tile 128x128, K-tile 64. 8 warps: wm=wid%4 (32 M rows), wn=wid/4 (64 N cols).
template<int KPAD, int NACT, int OSTRIDE, int RELU, int FINAL>
__global__ __launch_bounds__(256, 1) void hmma_gemm_kernel(
    const __nv_bfloat16* __restrict__ Ahi, const __nv_bfloat16* __restrict__ Alo,
    const __nv_bfloat16* __restrict__ Bhi, const __nv_bfloat16* __restrict__ Blo,
    const float* __restrict__ scale, const float* __restrict__ shift,
    __nv_bfloat16* __restrict__ Ohi, __nv_bfloat16* __restrict__ Olo,
    float* __restrict__ Ofin)
{
    constexpr int NC = KPAD / 64;
    constexpr int TILE_BYTES = 128 * 128;       // one 128x64 bf16 tile, 128B rows
    constexpr int STAGE_BYTES = 4 * TILE_BYTES; // Ah, Al, Bh, Bl

    extern __shared__ __align__(1024) char smem[];
    const uint32_t sbase = smem_u32(smem);
    const int tid = threadIdx.x;
    const int wid = tid >> 5;
    const int lane = tid & 31;
    const int wm = wid & 3;
    const int wn = wid >> 2;
    const int bm = blockIdx.y * 128;
    const int bn = blockIdx.x * 128;

    float acc[2][8][4];
    #pragma unroll
    for (int mt = 0; mt < 2; mt++)
        #pragma unroll
        for (int nt = 0; nt < 8; nt++)
            #pragma unroll
            for (int q = 0; q < 4; q++) acc[mt][nt][q] = 0.0f;

    // ---- async tile loader ----
    const __nv_bfloat16* aHrow = Ahi + (size_t)bm * KPAD;
    const __nv_bfloat16* aLrow = Alo + (size_t)bm * KPAD;
    const __nv_bfloat16* bHrow = Bhi + (size_t)bn * KPAD;
    const __nv_bfloat16* bLrow = Blo + (size_t)bn * KPAD;

    auto load_stage = [&](int c) {
        const uint32_t so = sbase + (uint32_t)(c & 1) * STAGE_BYTES;
        const int kc = c * 64;
        #pragma unroll
        for (int it = 0; it < 4; it++) {
            int i = tid + it * 256;
            int r = i >> 3, cc = i & 7;
            uint32_t sw = SWZ128((uint32_t)(r * 128 + cc * 16));
            size_t go = (size_t)r * KPAD + kc + cc * 8;
            CP_ASYNC16(so + sw,                  aHrow + go);
            CP_ASYNC16(so + TILE_BYTES + sw,     aLrow + go);
            CP_ASYNC16(so + 2 * TILE_BYTES + sw, bHrow + go);
            CP_ASYNC16(so + 3 * TILE_BYTES + sw, bLrow + go);
        }
    };

    load_stage(0);
    CP_COMMIT();

    #pragma unroll 1
    for (int c = 0; c < NC; c++) {
        if (c + 1 < NC) { load_stage(c + 1); CP_COMMIT(); CP_WAIT1(); }
        else            { CP_WAIT0(); }
        __syncthreads();

        const uint32_t st = sbase + (uint32_t)(c & 1) * STAGE_BYTES;
        const uint32_t sAh = st, sAl = st + TILE_BYTES;
        const uint32_t sBh = st + 2 * TILE_BYTES, sBl = st + 3 * TILE_BYTES;

        const int arow = wm * 32 + (lane & 15);
        const int brow = wn * 64 + ((lane >> 4) << 3) + (lane & 7);
        const uint32_t acol = (uint32_t)((lane >> 4) << 4);
        const uint32_t bcol = (uint32_t)(((lane >> 3) & 1) << 4);

        #pragma unroll
        for (int ks = 0; ks < 4; ks++) {
            uint32_t ah[2][4], al[2][4], bh[8][2], bl[8][2];
            #pragma unroll
            for (int mt = 0; mt < 2; mt++) {
                uint32_t off = SWZ128((uint32_t)((arow + mt * 16) * 128) + ks * 32 + acol);
                LDSM_X4(ah[mt], sAh + off);
                LDSM_X4(al[mt], sAl + off);
            }
            #pragma unroll
            for (int p = 0; p < 4; p++) {
                uint32_t off = SWZ128((uint32_t)((brow + p * 16) * 128) + ks * 32 + bcol);
                uint32_t r4[4];
                LDSM_X4(r4, sBh + off);
                bh[2 * p][0] = r4[0]; bh[2 * p][1] = r4[1];
                bh[2 * p + 1][0] = r4[2]; bh[2 * p + 1][1] = r4[3];
                LDSM_X4(r4, sBl + off);
                bl[2 * p][0] = r4[0]; bl[2 * p][1] = r4[1];
                bl[2 * p + 1][0] = r4[2]; bl[2 * p + 1][1] = r4[3];
            }
            #pragma unroll
            for (int mt = 0; mt < 2; mt++)
                #pragma unroll
                for (int nt = 0; nt < 8; nt++) {
                    mma_bf16(acc[mt][nt], ah[mt], bh[nt]);
                    mma_bf16(acc[mt][nt], ah[mt], bl[nt]);
                    mma_bf16(acc[mt][nt], al[mt], bh[nt]);
                }
        }
        __syncthreads();
    }

    // ---- epilogue ----
    if (!FINAL) {
        #pragma unroll
        for (int nt = 0; nt < 8; nt++) {
            int colg = bn + wn * 64 + nt * 8 + 2 * (lane & 3);
            if (colg >= OSTRIDE) continue;
            bool act0 = colg < NACT, act1 = (colg + 1) < NACT;
            float sc0 = act0 ? __ldg(scale + colg) : 0.f;
            float sh0 = act0 ? __ldg(shift + colg) : 0.f;
            float sc1 = act1 ? __ldg(scale + colg + 1) : 0.f;
            float sh1 = act1 ? __ldg(shift + colg + 1) : 0.f;
            #pragma unroll
            for (int mt = 0; mt < 2; mt++) {
                int r0 = bm + wm * 32 + mt * 16 + (lane >> 2);
                #pragma unroll
                for (int h = 0; h < 2; h++) {
                    int r = r0 + h * 8;
                    float v0 = act0 ? fmaf(acc[mt][nt][2 * h],     sc0, sh0) : 0.f;
                    float v1 = act1 ? fmaf(acc[mt][nt][2 * h + 1], sc1, sh1) : 0.f;
                    if (RELU) { v0 = fmaxf(v0, 0.f); v1 = fmaxf(v1, 0.f); }
                    __nv_bfloat16 h0 = __float2bfloat16(v0);
                    __nv_bfloat16 h1 = __float2bfloat16(v1);
                    __nv_bfloat16 l0 = __float2bfloat16(v0 - __bfloat162float(h0));
                    __nv_bfloat16 l1 = __float2bfloat16(v1 - __bfloat162float(h1));
                    uint32_t hp = (uint32_t)__bfloat16_as_ushort(h0) | ((uint32_t)__bfloat16_as_ushort(h1) << 16);
                    uint32_t lp = (uint32_t)__bfloat16_as_ushort(l0) | ((uint32_t)__bfloat16_as_ushort(l1) << 16);
                    size_t ro = (size_t)r * OSTRIDE + colg;
                    *(uint32_t*)(Ohi + ro) = hp;
                    *(uint32_t*)(Olo + ro) = lp;
                }
            }
        }
    } else {
        // BN then smem transpose, coalesced [b][n][s] store
        float* sf = (float*)smem;            // [128 n][132] floats
        #pragma unroll
        for (int nt = 0; nt < 8; nt++) {
            int coll = wn * 64 + nt * 8 + 2 * (lane & 3);
            int colg = bn + coll;
            float sc0 = __ldg(scale + colg),     sh0 = __ldg(shift + colg);
            float sc1 = __ldg(scale + colg + 1), sh1 = __ldg(shift + colg + 1);
            #pragma unroll
            for (int mt = 0; mt < 2; mt++) {
                int r0 = wm * 32 + mt * 16 + (lane >> 2);
                #pragma unroll
                for (int h = 0; h < 2; h++) {
                    int r = r0 + h * 8;
                    sf[(coll + 0) * 132 + r] = fmaf(acc[mt][nt][2 * h],     sc0, sh0);
                    sf[(coll + 1) * 132 + r] = fmaf(acc[mt][nt][2 * h + 1], sc1, sh1);
                }
            }
        }
        __syncthreads();
        #pragma unroll 1
        for (int i = tid; i < 128 * 128; i += 256) {
            int nl = i >> 7, ml = i & 127;
            int m = bm + ml;
            int b = m / SEGS;
            int s2 = m - b * SEGS;
            Ofin[(size_t)b * 768 * SEGS + (size_t)(bn + nl) * SEGS + s2] = sf[nl * 132 + ml];
        }
    }
}

// ================= launcher =================
extern "C" void kernel_launch(void* const* d_in, const int* in_sizes, int n_in,
                              void* d_out, int out_size)
{
    const float* x      = (const float*)d_in[0];
    const int*   sliced = (const int*)d_in[1];
    const float *W[5], *Bb[5], *G[5], *Be[5], *Rm[5], *Rv[5];
    for (int i = 0; i < 5; i++) {
        int k = 2 + i * 6;
        W[i]  = (const float*)d_in[k + 0];
        Bb[i] = (const float*)d_in[k + 1];
        G[i]  = (const float*)d_in[k + 2];
        Be[i] = (const float*)d_in[k + 3];
        Rm[i] = (const float*)d_in[k + 4];
        Rv[i] = (const float*)d_in[k + 5];
    }
    float* out = (float*)d_out;

    void *accP, *h0P, *l0P, *h1P, *l1P, *whiP, *wloP, *scP, *shP;
    cudaGetSymbolAddress(&accP, g_acc);
    cudaGetSymbolAddress(&h0P, g_hi0);
    cudaGetSymbolAddress(&l0P, g_lo0);
    cudaGetSymbolAddress(&h1P, g_hi1);
    cudaGetSymbolAddress(&l1P, g_lo1);
    cudaGetSymbolAddress(&whiP, g_whi);
    cudaGetSymbolAddress(&wloP, g_wlo);
    cudaGetSymbolAddress(&scP, g_scale);
    cudaGetSymbolAddress(&shP, g_shift);
    float* acc = (float*)accP;
    __nv_bfloat16* hi0 = (__nv_bfloat16*)h0P;
    __nv_bfloat16* lo0 = (__nv_bfloat16*)l0P;
    __nv_bfloat16* hi1 = (__nv_bfloat16*)h1P;
    __nv_bfloat16* lo1 = (__nv_bfloat16*)l1P;
    __nv_bfloat16* whi = (__nv_bfloat16*)whiP;
    __nv_bfloat16* wlo = (__nv_bfloat16*)wloP;
    float* sc = (float*)scP;
    float* sh = (float*)shP;

    cudaMemsetAsync(accP, 0, sizeof(float) * 9 * M_ROWS, 0);

    seg_acc_kernel<<<dim3(8, BATCH), 256>>>(x, sliced, out, acc);
    finalize_kernel<<<(M_ROWS + 255) / 256, 256>>>(acc, x, hi0, lo0);

    const int NL[5]  = {96, 192, 384, 768, 768};
    const int KL[5]  = {11, 96, 192, 384, 768};
    const int NP[5]  = {128, 256, 384, 768, 768};
    const int KP[5]  = {64, 128, 192, 384, 768};
    const int WOFF[5] = {0, 8192, 40960, 114688, 409600};
    const int SOFF[5] = {0, 96, 288, 672, 1440};
    for (int i = 0; i < 5; i++) {
        int cnt = NP[i] * KP[i];
        conv_w_kernel<<<(cnt + 255) / 256, 256>>>(W[i], whi + WOFF[i], wlo + WOFF[i],
                                                  NL[i], KL[i], NP[i], KP[i]);
        bnpar_kernel<<<(NL[i] + 255) / 256, 256>>>(G[i], Be[i], Rm[i], Rv[i], Bb[i],
                                                   NL[i], sc + SOFF[i], sh + SOFF[i]);
    }

    const int SMEM = 2 * 4 * 128 * 128;   // 131072

    // L0: K=64 (padded from 11), N 96 -> stride 128 out (zero-padded 96..127)
    cudaFuncSetAttribute(hmma_gemm_kernel<64, 96, 128, 1, 0>,
                         cudaFuncAttributeMaxDynamicSharedMemorySize, SMEM);
    hmma_gemm_kernel<64, 96, 128, 1, 0><<<dim3(1, 196), 256, SMEM>>>(
        hi0, lo0, whi + WOFF[0], wlo + WOFF[0], sc + SOFF[0], sh + SOFF[0], hi1, lo1, nullptr);

    // L1: K=128 (96 padded), N 192 -> stride 192
    cudaFuncSetAttribute(hmma_gemm_kernel<128, 192, 192, 1, 0>,
                         cudaFuncAttributeMaxDynamicSharedMemorySize, SMEM);
    hmma_gemm_kernel<128, 192, 192, 1, 0><<<dim3(2, 196), 256, SMEM>>>(
        hi1, lo1, whi + WOFF[1], wlo + WOFF[1], sc + SOFF[1], sh + SOFF[1], hi0, lo0, nullptr);

    // L2: K=192, N 384 -> stride 384
    cudaFuncSetAttribute(hmma_gemm_kernel<192, 384, 384, 1, 0>,
                         cudaFuncAttributeMaxDynamicSharedMemorySize, SMEM);
    hmma_gemm_kernel<192, 384, 384, 1, 0><<<dim3(3, 196), 256, SMEM>>>(
        hi0, lo0, whi + WOFF[2], wlo + WOFF[2], sc + SOFF[2], sh + SOFF[2], hi1, lo1, nullptr);

    // L3: K=384, N 768 -> stride 768
    cudaFuncSetAttribute(hmma_gemm_kernel<384, 768, 768, 1, 0>,
                         cudaFuncAttributeMaxDynamicSharedMemorySize, SMEM);
    hmma_gemm_kernel<384, 768, 768, 1, 0><<<dim3(6, 196), 256, SMEM>>>(
        hi1, lo1, whi + WOFF[3], wlo + WOFF[3], sc + SOFF[3], sh + SOFF[3], hi0, lo0, nullptr);

    // L4: K=768, N 768, final -> transposed fp32 out
    cudaFuncSetAttribute(hmma_gemm_kernel<768, 768, 768, 0, 1>,
                         cudaFuncAttributeMaxDynamicSharedMemorySize, SMEM);
    hmma_gemm_kernel<768, 768, 768, 0, 1><<<dim3(6, 196), 256, SMEM>>>(
        hi0, lo0, whi + WOFF[4], wlo + WOFF[4], sc + SOFF[4], sh + SOFF[4], nullptr, nullptr,
        out + OUT_SLICED_ELEMS);
}

// round 7
// speedup vs baseline: 2.3356x; 1.0427x over previous
#include <cuda_runtime.h>
#include <cuda_bf16.h>
#include <math.h>
#include <stdint.h>

// ---------------- problem constants ----------------
#define BATCH 128
#define SEGS  196
#define HW    224
#define NPIX  (HW*HW)
#define M_ROWS (BATCH*SEGS)      // 25088 = 256*98
#define BN_EPS 1e-5f
#define OUT_SLICED_ELEMS ((size_t)BATCH*NPIX)

// ================= helpers =================
__device__ __forceinline__ uint32_t smem_u32(const void* p) {
    uint32_t a;
    asm("{ .reg .u64 t; cvta.to.shared.u64 t, %1; cvt.u32.u64 %0, t; }" : "=r"(a) : "l"(p));
    return a;
}
#define SWZ128(off) ((off) ^ (((off) >> 3) & 0x70))

#define CP_ASYNC16(saddr, gptr) \
    asm volatile("cp.async.cg.shared.global [%0], [%1], 16;" :: "r"(saddr), "l"(gptr))
#define CP_COMMIT() asm volatile("cp.async.commit_group;" ::: "memory")
#define CP_WAIT0()  asm volatile("cp.async.wait_group 0;" ::: "memory")
#define CP_WAIT1()  asm volatile("cp.async.wait_group 1;" ::: "memory")

#define LDSM_X4(r, addr) \
    asm volatile("ldmatrix.sync.aligned.m8n8.x4.shared.b16 {%0,%1,%2,%3}, [%4];" \
        : "=r"((r)[0]), "=r"((r)[1]), "=r"((r)[2]), "=r"((r)[3]) : "r"(addr))

__device__ __forceinline__ void mma_bf16(float* c, const uint32_t* a, const uint32_t* b) {
    asm volatile(
        "mma.sync.aligned.m16n8k16.row.col.f32.bf16.bf16.f32 "
        "{%0,%1,%2,%3}, {%4,%5,%6,%7}, {%8,%9}, {%0,%1,%2,%3};"
        : "+f"(c[0]), "+f"(c[1]), "+f"(c[2]), "+f"(c[3])
        : "r"(a[0]), "r"(a[1]), "r"(a[2]), "r"(a[3]), "r"(b[0]), "r"(b[1]));
}

// ================= scratch (device globals) =================
__device__ float g_acc[9 * M_ROWS];
__device__ __nv_bfloat16 g_hi0[(size_t)M_ROWS * 768];
__device__ __nv_bfloat16 g_lo0[(size_t)M_ROWS * 768];
__device__ __nv_bfloat16 g_hi1[(size_t)M_ROWS * 768];
__device__ __nv_bfloat16 g_lo1[(size_t)M_ROWS * 768];
__device__ __nv_bfloat16 g_whi[999424];
__device__ __nv_bfloat16 g_wlo[999424];
__device__ float g_scale[2208];
__device__ float g_shift[2208];

// ================= segment accumulation =================
__global__ __launch_bounds__(256) void seg_acc_kernel(
    const float* __restrict__ x, const int* __restrict__ sliced,
    float* __restrict__ outSliced, float* __restrict__ acc)
{
    __shared__ float s[SEGS * 9];
    const int b = blockIdx.y;
    for (int i = threadIdx.x; i < SEGS * 9; i += blockDim.x) s[i] = 0.0f;
    __syncthreads();

    const int chunk = NPIX / gridDim.x;
    const int p0 = blockIdx.x * chunk;
    const float* xb = x + (size_t)b * 3 * NPIX;
    const int* sb = sliced + (size_t)b * NPIX;
    float* ob = outSliced + (size_t)b * NPIX;

    for (int p = p0 + threadIdx.x; p < p0 + chunk; p += blockDim.x) {
        int sid = sb[p];
        ob[p] = (float)sid;
        float r = (float)(p / HW);
        float c = (float)(p % HW);
        float v0 = xb[p], v1 = xb[NPIX + p], v2 = xb[2 * NPIX + p];
        float* a9 = s + sid * 9;
        atomicAdd(a9 + 0, 1.0f);
        atomicAdd(a9 + 1, r);
        atomicAdd(a9 + 2, c);
        atomicAdd(a9 + 3, v0);
        atomicAdd(a9 + 4, v1);
        atomicAdd(a9 + 5, v2);
        atomicAdd(a9 + 6, v0 * v0);
        atomicAdd(a9 + 7, v1 * v1);
        atomicAdd(a9 + 8, v2 * v2);
    }
    __syncthreads();
    for (int i = threadIdx.x; i < SEGS * 9; i += blockDim.x) {
        int sid = i / 9, f = i % 9;
        float v = s[i];
        if (v != 0.0f) atomicAdd(&acc[(size_t)f * M_ROWS + b * SEGS + sid], v);
    }
}

// ================= finalize -> bf16 hi/lo feature matrix (stride 64) =================
__global__ __launch_bounds__(256) void finalize_kernel(
    const float* __restrict__ acc, const float* __restrict__ x,
    __nv_bfloat16* __restrict__ fhi, __nv_bfloat16* __restrict__ flo)
{
    int idx = blockIdx.x * blockDim.x + threadIdx.x;
    if (idx >= M_ROWS) return;
    int b = idx / SEGS;

    float cnt  = acc[idx];
    float inv  = 1.0f / fmaxf(cnt, 1.0f);
    float mrow = acc[(size_t)1 * M_ROWS + idx] * inv;
    float mcol = acc[(size_t)2 * M_ROWS + idx] * inv;
    float m0 = acc[(size_t)3 * M_ROWS + idx] * inv;
    float m1 = acc[(size_t)4 * M_ROWS + idx] * inv;
    float m2 = acc[(size_t)5 * M_ROWS + idx] * inv;
    float dn = 1.0f / fmaxf(cnt - 1.0f, 1.0f);
    float v0 = (acc[(size_t)6 * M_ROWS + idx] - cnt * m0 * m0) * dn;
    float v1 = (acc[(size_t)7 * M_ROWS + idx] - cnt * m1 * m1) * dn;
    float v2 = (acc[(size_t)8 * M_ROWS + idx] - cnt * m2 * m2) * dn;
    float sd0 = (cnt > 1.0f) ? sqrtf(fmaxf(v0, 0.0f)) : 0.0f;
    float sd1 = (cnt > 1.0f) ? sqrtf(fmaxf(v1, 0.0f)) : 0.0f;
    float sd2 = (cnt > 1.0f) ? sqrtf(fmaxf(v2, 0.0f)) : 0.0f;

    int ri = min(max((int)mrow, 0), HW - 1);
    int ci = min(max((int)mcol, 0), HW - 1);
    const float* xb = x + (size_t)b * 3 * NPIX;
    int pp = ri * HW + ci;
    float mask = (cnt > 0.0f) ? 1.0f : 0.0f;

    float f[11];
    f[0] = mrow * mask; f[1] = mcol * mask;
    f[2] = m0 * mask;   f[3] = m1 * mask;   f[4] = m2 * mask;
    f[5] = sd0 * mask;  f[6] = sd1 * mask;  f[7] = sd2 * mask;
    f[8] = xb[pp] * mask; f[9] = xb[NPIX + pp] * mask; f[10] = xb[2 * NPIX + pp] * mask;

    __nv_bfloat16* ph = fhi + (size_t)idx * 64;
    __nv_bfloat16* pl = flo + (size_t)idx * 64;
    #pragma unroll
    for (int c = 0; c < 11; c++) {
        __nv_bfloat16 h = __float2bfloat16(f[c]);
        ph[c] = h;
        pl[c] = __float2bfloat16(f[c] - __bfloat162float(h));
    }
    for (int c = 11; c < 64; c++) { ph[c] = __float2bfloat16(0.f); pl[c] = __float2bfloat16(0.f); }
}

// ================= fused prep: weight hi/lo convert + BN params (1 launch) =================
struct PrepArgs {
    const float* w[5];
    const float* bb[5];
    const float* g[5];
    const float* be[5];
    const float* rm[5];
    const float* rv[5];
};

__global__ __launch_bounds__(256) void prep_kernel(
    PrepArgs a, __nv_bfloat16* __restrict__ whi, __nv_bfloat16* __restrict__ wlo,
    float* __restrict__ sc, float* __restrict__ sh)
{
    const int NLc[5] = {96, 192, 384, 768, 768};
    const int KLc[5] = {11, 96, 192, 384, 768};
    const int KPc[5] = {64, 128, 192, 384, 768};
    const int WOFFc[6] = {0, 8192, 40960, 114688, 409600, 999424};
    const int SOFFc[6] = {0, 96, 288, 672, 1440, 2208};

    const int stride = gridDim.x * blockDim.x;
    int idx = blockIdx.x * blockDim.x + threadIdx.x;

    for (int i = idx; i < 999424; i += stride) {
        int L = 0;
        while (i >= WOFFc[L + 1]) L++;
        int off = i - WOFFc[L];
        int n = off / KPc[L], k = off - n * KPc[L];
        float v = (n < NLc[L] && k < KLc[L]) ? a.w[L][n * KLc[L] + k] : 0.0f;
        __nv_bfloat16 h = __float2bfloat16(v);
        whi[i] = h;
        wlo[i] = __float2bfloat16(v - __bfloat162float(h));
    }
    for (int i = idx; i < 2208; i += stride) {
        int L = 0;
        while (i >= SOFFc[L + 1]) L++;
        int n = i - SOFFc[L];
        float s = a.g[L][n] * rsqrtf(a.rv[L][n] + BN_EPS);
        sc[i] = s;
        sh[i] = (a.bb[L][n] - a.rm[L][n]) * s + a.be[L][n];
    }
}

// ================= split-bf16 HMMA GEMM + BN epilogue =================
// CTA tile 256x128, K-tile 64. 16 warps: wm=wid&7 (32 M rows), wn=wid>>3 (64 N cols).
template<int KPAD, int NACT, int OSTRIDE, int RELU, int FINAL>
__global__ __launch_bounds__(512, 1) void hmma_gemm_kernel(
    const __nv_bfloat16* __restrict__ Ahi, const __nv_bfloat16* __restrict__ Alo,
    const __nv_bfloat16* __restrict__ Bhi, const __nv_bfloat16* __restrict__ Blo,
    const float* __restrict__ scale, const float* __restrict__ shift,
    __nv_bfloat16* __restrict__ Ohi, __nv_bfloat16* __restrict__ Olo,
    float* __restrict__ Ofin)
{
    constexpr int NC = KPAD / 64;
    constexpr int A_BYTES = 256 * 128;          // 256 rows x 128B (one of hi/lo)
    constexpr int B_BYTES = 128 * 128;
    constexpr int STAGE_BYTES = 2 * A_BYTES + 2 * B_BYTES;  // 98304

    extern __shared__ __align__(1024) char smem[];
    const uint32_t sbase = smem_u32(smem);
    const int tid = threadIdx.x;
    const int wid = tid >> 5;
    const int lane = tid & 31;
    const int wm = wid & 7;
    const int wn = wid >> 3;
    const int bm = blockIdx.y * 256;
    const int bn = blockIdx.x * 128;

    float acc[2][8][4];
    #pragma unroll
    for (int mt = 0; mt < 2; mt++)
        #pragma unroll
        for (int nt = 0; nt < 8; nt++)
            #pragma unroll
            for (int q = 0; q < 4; q++) acc[mt][nt][q] = 0.0f;

    const __nv_bfloat16* aHrow = Ahi + (size_t)bm * KPAD;
    const __nv_bfloat16* aLrow = Alo + (size_t)bm * KPAD;
    const __nv_bfloat16* bHrow = Bhi + (size_t)bn * KPAD;
    const __nv_bfloat16* bLrow = Blo + (size_t)bn * KPAD;

    auto load_stage = [&](int c) {
        const uint32_t so = sbase + (uint32_t)(c & 1) * STAGE_BYTES;
        const int kc = c * 64;
        #pragma unroll
        for (int it = 0; it < 4; it++) {          // A: 2048 16B transfers
            int i = tid + it * 512;
            int r = i >> 3, cc = i & 7;
            uint32_t sw = SWZ128((uint32_t)((r & 255) * 128 + cc * 16));
            size_t go = (size_t)r * KPAD + kc + cc * 8;
            CP_ASYNC16(so + sw,           aHrow + go);
            CP_ASYNC16(so + A_BYTES + sw, aLrow + go);
        }
        #pragma unroll
        for (int it = 0; it < 2; it++) {          // B: 1024 16B transfers
            int i = tid + it * 512;
            int r = i >> 3, cc = i & 7;
            uint32_t sw = SWZ128((uint32_t)(r * 128 + cc * 16));
            size_t go = (size_t)r * KPAD + kc + cc * 8;
            CP_ASYNC16(so + 2 * A_BYTES + sw,           bHrow + go);
            CP_ASYNC16(so + 2 * A_BYTES + B_BYTES + sw, bLrow + go);
        }
    };

    load_stage(0);
    CP_COMMIT();

    #pragma unroll 1
    for (int c = 0; c < NC; c++) {
        if (c + 1 < NC) { load_stage(c + 1); CP_COMMIT(); CP_WAIT1(); }
        else            { CP_WAIT0(); }
        __syncthreads();

        const uint32_t st = sbase + (uint32_t)(c & 1) * STAGE_BYTES;
        const uint32_t sAh = st, sAl = st + A_BYTES;
        const uint32_t sBh = st + 2 * A_BYTES, sBl = st + 2 * A_BYTES + B_BYTES;

        const int arow = wm * 32 + (lane & 15);
        const int brow = wn * 64 + ((lane >> 4) << 3) + (lane & 7);
        const uint32_t acol = (uint32_t)((lane >> 4) << 4);
        const uint32_t bcol = (uint32_t)(((lane >> 3) & 1) << 4);

        #pragma unroll
        for (int ks = 0; ks < 4; ks++) {
            uint32_t ah[2][4], al[2][4], bh[8][2], bl[8][2];
            #pragma unroll
            for (int mt = 0; mt < 2; mt++) {
                uint32_t off = SWZ128((uint32_t)((arow + mt * 16) * 128) + ks * 32 + acol);
                LDSM_X4(ah[mt], sAh + off);
                LDSM_X4(al[mt], sAl + off);
            }
            #pragma unroll
            for (int p = 0; p < 4; p++) {
                uint32_t off = SWZ128((uint32_t)((brow + p * 16) * 128) + ks * 32 + bcol);
                uint32_t r4[4];
                LDSM_X4(r4, sBh + off);
                bh[2 * p][0] = r4[0]; bh[2 * p][1] = r4[1];
                bh[2 * p + 1][0] = r4[2]; bh[2 * p + 1][1] = r4[3];
                LDSM_X4(r4, sBl + off);
                bl[2 * p][0] = r4[0]; bl[2 * p][1] = r4[1];
                bl[2 * p + 1][0] = r4[2]; bl[2 * p + 1][1] = r4[3];
            }
            #pragma unroll
            for (int mt = 0; mt < 2; mt++)
                #pragma unroll
                for (int nt = 0; nt < 8; nt++) {
                    mma_bf16(acc[mt][nt], ah[mt], bh[nt]);
                    mma_bf16(acc[mt][nt], ah[mt], bl[nt]);
                    mma_bf16(acc[mt][nt], al[mt], bh[nt]);
                }
        }
        __syncthreads();
    }

    // ---- epilogue ----
    if (!FINAL) {
        #pragma unroll
        for (int nt = 0; nt < 8; nt++) {
            int colg = bn + wn * 64 + nt * 8 + 2 * (lane & 3);
            if (colg >= OSTRIDE) continue;
            bool act0 = colg < NACT, act1 = (colg + 1) < NACT;
            float sc0 = act0 ? __ldg(scale + colg) : 0.f;
            float sh0 = act0 ? __ldg(shift + colg) : 0.f;
            float sc1 = act1 ? __ldg(scale + colg + 1) : 0.f;
            float sh1 = act1 ? __ldg(shift + colg + 1) : 0.f;
            #pragma unroll
            for (int mt = 0; mt < 2; mt++) {
                int r0 = bm + wm * 32 + mt * 16 + (lane >> 2);
                #pragma unroll
                for (int h = 0; h < 2; h++) {
                    int r = r0 + h * 8;
                    float v0 = act0 ? fmaf(acc[mt][nt][2 * h],     sc0, sh0) : 0.f;
                    float v1 = act1 ? fmaf(acc[mt][nt][2 * h + 1], sc1, sh1) : 0.f;
                    if (RELU) { v0 = fmaxf(v0, 0.f); v1 = fmaxf(v1, 0.f); }
                    __nv_bfloat16 h0 = __float2bfloat16(v0);
                    __nv_bfloat16 h1 = __float2bfloat16(v1);
                    __nv_bfloat16 l0 = __float2bfloat16(v0 - __bfloat162float(h0));
                    __nv_bfloat16 l1 = __float2bfloat16(v1 - __bfloat162float(h1));
                    uint32_t hp = (uint32_t)__bfloat16_as_ushort(h0) | ((uint32_t)__bfloat16_as_ushort(h1) << 16);
                    uint32_t lp = (uint32_t)__bfloat16_as_ushort(l0) | ((uint32_t)__bfloat16_as_ushort(l1) << 16);
                    size_t ro = (size_t)r * OSTRIDE + colg;
                    *(uint32_t*)(Ohi + ro) = hp;
                    *(uint32_t*)(Olo + ro) = lp;
                }
            }
        }
    } else {
        // BN then smem transpose, coalesced [b][n][s] store
        float* sf = (float*)smem;            // [128 n][260] floats
        #pragma unroll
        for (int nt = 0; nt < 8; nt++) {
            int coll = wn * 64 + nt * 8 + 2 * (lane & 3);
            int colg = bn + coll;
            float sc0 = __ldg(scale + colg),     sh0 = __ldg(shift + colg);
            float sc1 = __ldg(scale + colg + 1), sh1 = __ldg(shift + colg + 1);
            #pragma unroll
            for (int mt = 0; mt < 2; mt++) {
                int r0 = wm * 32 + mt * 16 + (lane >> 2);
                #pragma unroll
                for (int h = 0; h < 2; h++) {
                    int r = r0 + h * 8;
                    sf[(coll + 0) * 260 + r] = fmaf(acc[mt][nt][2 * h],     sc0, sh0);
                    sf[(coll + 1) * 260 + r] = fmaf(acc[mt][nt][2 * h + 1], sc1, sh1);
                }
            }
        }
        __syncthreads();
        #pragma unroll 1
        for (int i = tid; i < 128 * 256; i += 512) {
            int nl = i >> 8, ml = i & 255;
            int m = bm + ml;
            int b = m / SEGS;
            int s2 = m - b * SEGS;
            Ofin[(size_t)b * 768 * SEGS + (size_t)(bn + nl) * SEGS + s2] = sf[nl * 260 + ml];
        }
    }
}

// ================= launcher =================
extern "C" void kernel_launch(void* const* d_in, const int* in_sizes, int n_in,
                              void* d_out, int out_size)
{
    const float* x      = (const float*)d_in[0];
    const int*   sliced = (const int*)d_in[1];
    PrepArgs pa;
    for (int i = 0; i < 5; i++) {
        int k = 2 + i * 6;
        pa.w[i]  = (const float*)d_in[k + 0];
        pa.bb[i] = (const float*)d_in[k + 1];
        pa.g[i]  = (const float*)d_in[k + 2];
        pa.be[i] = (const float*)d_in[k + 3];
        pa.rm[i] = (const float*)d_in[k + 4];
        pa.rv[i] = (const float*)d_in[k + 5];
    }
    float* out = (float*)d_out;

    void *accP, *h0P, *l0P, *h1P, *l1P, *whiP, *wloP, *scP, *shP;
    cudaGetSymbolAddress(&accP, g_acc);
    cudaGetSymbolAddress(&h0P, g_hi0);
    cudaGetSymbolAddress(&l0P, g_lo0);
    cudaGetSymbolAddress(&h1P, g_hi1);
    cudaGetSymbolAddress(&l1P, g_lo1);
    cudaGetSymbolAddress(&whiP, g_whi);
    cudaGetSymbolAddress(&wloP, g_wlo);
    cudaGetSymbolAddress(&scP, g_scale);
    cudaGetSymbolAddress(&shP, g_shift);
    float* acc = (float*)accP;
    __nv_bfloat16* hi0 = (__nv_bfloat16*)h0P;
    __nv_bfloat16* lo0 = (__nv_bfloat16*)l0P;
    __nv_bfloat16* hi1 = (__nv_bfloat16*)h1P;
    __nv_bfloat16* lo1 = (__nv_bfloat16*)l1P;
    __nv_bfloat16* whi = (__nv_bfloat16*)whiP;
    __nv_bfloat16* wlo = (__nv_bfloat16*)wloP;
    float* sc = (float*)scP;
    float* sh = (float*)shP;

    cudaMemsetAsync(accP, 0, sizeof(float) * 9 * M_ROWS, 0);

    seg_acc_kernel<<<dim3(8, BATCH), 256>>>(x, sliced, out, acc);
    finalize_kernel<<<(M_ROWS + 255) / 256, 256>>>(acc, x, hi0, lo0);
    prep_kernel<<<592, 256>>>(pa, whi, wlo, sc, sh);

    const int WOFF[5] = {0, 8192, 40960, 114688, 409600};
    const int SOFF[5] = {0, 96, 288, 672, 1440};
    const int SMEM = 2 * 98304;   // 196608

    const int MB = M_ROWS / 256;  // 98

    // L0: K=64 (padded from 11), N 96 -> stride 128 out (zero-padded 96..127)
    cudaFuncSetAttribute(hmma_gemm_kernel<64, 96, 128, 1, 0>,
                         cudaFuncAttributeMaxDynamicSharedMemorySize, SMEM);
    hmma_gemm_kernel<64, 96, 128, 1, 0><<<dim3(1, MB), 512, SMEM>>>(
        hi0, lo0, whi + WOFF[0], wlo + WOFF[0], sc + SOFF[0], sh + SOFF[0], hi1, lo1, nullptr);

    // L1: K=128 (96 padded), N 192 -> stride 192
    cudaFuncSetAttribute(hmma_gemm_kernel<128, 192, 192, 1, 0>,
                         cudaFuncAttributeMaxDynamicSharedMemorySize, SMEM);
    hmma_gemm_kernel<128, 192, 192, 1, 0><<<dim3(2, MB), 512, SMEM>>>(
        hi1, lo1, whi + WOFF[1], wlo + WOFF[1], sc + SOFF[1], sh + SOFF[1], hi0, lo0, nullptr);

    // L2: K=192, N 384 -> stride 384
    cudaFuncSetAttribute(hmma_gemm_kernel<192, 384, 384, 1, 0>,
                         cudaFuncAttributeMaxDynamicSharedMemorySize, SMEM);
    hmma_gemm_kernel<192, 384, 384, 1, 0><<<dim3(3, MB), 512, SMEM>>>(
        hi0, lo0, whi + WOFF[2], wlo + WOFF[2], sc + SOFF[2], sh + SOFF[2], hi1, lo1, nullptr);

    // L3: K=384, N 768 -> stride 768
    cudaFuncSetAttribute(hmma_gemm_kernel<384, 768, 768, 1, 0>,
                         cudaFuncAttributeMaxDynamicSharedMemorySize, SMEM);
    hmma_gemm_kernel<384, 768, 768, 1, 0><<<dim3(6, MB), 512, SMEM>>>(
        hi1, lo1, whi + WOFF[3], wlo + WOFF[3], sc + SOFF[3], sh + SOFF[3], hi0, lo0, nullptr);

    // L4: K=768, N 768, final -> transposed fp32 out
    cudaFuncSetAttribute(hmma_gemm_kernel<768, 768, 768, 0, 1>,
                         cudaFuncAttributeMaxDynamicSharedMemorySize, SMEM);
    hmma_gemm_kernel<768, 768, 768, 0, 1><<<dim3(6, MB), 512, SMEM>>>(
        hi0, lo0, whi + WOFF[4], wlo + WOFF[4], sc + SOFF[4], sh + SOFF[4], nullptr, nullptr,
        out + OUT_SLICED_ELEMS);
}